// round 6
// baseline (speedup 1.0000x reference)
#include <cuda_runtime.h>
#include <cuda_fp16.h>

#define N_NODES 50000
#define D 32
#define D4 8

// Scratch (device globals — no allocation allowed).
__device__ float  g_seg[N_NODES * D];   // step1 fp32 accumulator
__device__ float  g_deg[N_NODES];       // in-degree
__device__ float  g_g[N_NODES * D];     // fp32 accumulator: b/2 + sum 0.5*(mW)[src]
__device__ __half g_sh[N_NODES * D];    // fp16 copy of 0.5*(m W^T)  (K4 gather table)
__device__ __half g_gh[N_NODES * D];    // fp16 copy of g_g          (K5 gather table)

__device__ __forceinline__ void red_add_v4(float* ptr, float4 v) {
    asm volatile("red.global.add.v4.f32 [%0], {%1, %2, %3, %4};"
                 :: "l"(ptr), "f"(v.x), "f"(v.y), "f"(v.z), "f"(v.w)
                 : "memory");
}

__device__ __forceinline__ float4 ld_cs_v4(const float4* ptr) {
    float4 v;
    asm volatile("ld.global.cs.v4.f32 {%0, %1, %2, %3}, [%4];"
                 : "=f"(v.x), "=f"(v.y), "=f"(v.z), "=f"(v.w) : "l"(ptr));
    return v;
}

__device__ __forceinline__ void st_cs_v4(float4* ptr, float4 v) {
    asm volatile("st.global.cs.v4.f32 [%0], {%1, %2, %3, %4};"
                 :: "l"(ptr), "f"(v.x), "f"(v.y), "f"(v.z), "f"(v.w)
                 : "memory");
}

// ---------------------------------------------------------------------------
// K1: g_seg = 0, deg = 0
// ---------------------------------------------------------------------------
__global__ void k_zero() {
    int i = blockIdx.x * blockDim.x + threadIdx.x;   // over N_NODES * D4
    if (i < N_NODES * D4)
        ((float4*)g_seg)[i] = make_float4(0.f, 0.f, 0.f, 0.f);
    if (i < N_NODES) g_deg[i] = 0.0f;
}

// ---------------------------------------------------------------------------
// K2: seg[dst] += ef[e]; deg[dst] += 1.  8 threads/edge (float4), ILP=2.
// ---------------------------------------------------------------------------
__global__ void k_scatter_feats(const float4* __restrict__ ef,
                                const int* __restrict__ dst, int E, int half) {
    int t = blockIdx.x * blockDim.x + threadIdx.x;   // over half * D4
    if (t >= half * D4) return;
    int e  = t >> 3;
    int d4 = t & 7;
    int e2 = e + half;

    float4 v0 = ld_cs_v4(&ef[e * D4 + d4]);
    int n0 = dst[e];
    if (e2 < E) {
        float4 v1 = ld_cs_v4(&ef[e2 * D4 + d4]);
        int n1 = dst[e2];
        red_add_v4(&g_seg[n0 * D + d4 * 4], v0);
        red_add_v4(&g_seg[n1 * D + d4 * 4], v1);
        if (d4 == 0) {
            atomicAdd(&g_deg[n0], 1.0f);
            atomicAdd(&g_deg[n1], 1.0f);
        }
    } else {
        red_add_v4(&g_seg[n0 * D + d4 * 4], v0);
        if (d4 == 0) atomicAdd(&g_deg[n0], 1.0f);
    }
}

// ---------------------------------------------------------------------------
// K3: m = seg/max(deg,1); g_sh row <- fp16(0.5 * m @ W^T); g_g row <- b/2.
// Warp per node.
// ---------------------------------------------------------------------------
__global__ void k_norm_gemm(const float* __restrict__ W,
                            const float* __restrict__ b) {
    __shared__ float Ws[D * (D + 1)];
    __shared__ float ms[8][D];
    for (int i = threadIdx.x; i < D * D; i += blockDim.x)
        Ws[(i / D) * (D + 1) + (i % D)] = W[i];
    __syncthreads();

    int w = (blockIdx.x * blockDim.x + threadIdx.x) >> 5;
    if (w >= N_NODES) return;
    int lane = threadIdx.x & 31;
    int wib  = (threadIdx.x >> 5) & 7;

    float inv = 1.0f / fmaxf(g_deg[w], 1.0f);
    ms[wib][lane] = g_seg[w * D + lane] * inv;
    __syncwarp();
    float acc = 0.0f;
#pragma unroll
    for (int k = 0; k < D; k++)
        acc = fmaf(ms[wib][k], Ws[lane * (D + 1) + k], acc);
    g_sh[w * D + lane] = __float2half(0.5f * acc);
    g_g[w * D + lane]  = 0.5f * b[lane];             // bias/2 pre-init
}

// ---------------------------------------------------------------------------
// K4: g_g[dst] += s[src]  — gather fp16 quarter-rows (16B = 8 halfs), red fp32.
// 4 threads/edge, ILP=2.
// ---------------------------------------------------------------------------
__global__ void k_gather_scatter(const int* __restrict__ src,
                                 const int* __restrict__ dst, int E, int half) {
    int t = blockIdx.x * blockDim.x + threadIdx.x;   // over half * 4
    if (t >= half * 4) return;
    int e = t >> 2;
    int q = t & 3;
    int e2 = e + half;

    {
        int ns = src[e];
        int nd = dst[e];
        uint4 raw = *(const uint4*)&g_sh[ns * D + q * 8];
        float2 f0 = __half22float2(*(__half2*)&raw.x);
        float2 f1 = __half22float2(*(__half2*)&raw.y);
        float2 f2 = __half22float2(*(__half2*)&raw.z);
        float2 f3 = __half22float2(*(__half2*)&raw.w);
        red_add_v4(&g_g[nd * D + q * 8],     make_float4(f0.x, f0.y, f1.x, f1.y));
        red_add_v4(&g_g[nd * D + q * 8 + 4], make_float4(f2.x, f2.y, f3.x, f3.y));
    }
    if (e2 < E) {
        int ns = src[e2];
        int nd = dst[e2];
        uint4 raw = *(const uint4*)&g_sh[ns * D + q * 8];
        float2 f0 = __half22float2(*(__half2*)&raw.x);
        float2 f1 = __half22float2(*(__half2*)&raw.y);
        float2 f2 = __half22float2(*(__half2*)&raw.z);
        float2 f3 = __half22float2(*(__half2*)&raw.w);
        red_add_v4(&g_g[nd * D + q * 8],     make_float4(f0.x, f0.y, f1.x, f1.y));
        red_add_v4(&g_g[nd * D + q * 8 + 4], make_float4(f2.x, f2.y, f3.x, f3.y));
    }
}

// ---------------------------------------------------------------------------
// K4b: convert g_g -> fp16 copy for the K5 gathers (6.4MB read, 3.2MB write)
// ---------------------------------------------------------------------------
__global__ void k_cvt() {
    int i = blockIdx.x * blockDim.x + threadIdx.x;   // over N_NODES * D / 8
    if (i >= N_NODES * D / 8) return;
    float4 a = ((const float4*)g_g)[2 * i];
    float4 c = ((const float4*)g_g)[2 * i + 1];
    uint4 o;
    *(__half2*)&o.x = __floats2half2_rn(a.x, a.y);
    *(__half2*)&o.y = __floats2half2_rn(a.z, a.w);
    *(__half2*)&o.z = __floats2half2_rn(c.x, c.y);
    *(__half2*)&o.w = __floats2half2_rn(c.z, c.w);
    ((uint4*)g_gh)[i] = o;
}

// ---------------------------------------------------------------------------
// K5: out[e] = g[src[e]] + g[dst[e]]  (fp16 gathers, fp32 add+store), ILP=2.
// 4 threads/edge: 2x 16B gathers, 2x 16B stores per thread.
// ---------------------------------------------------------------------------
__global__ void k_edge_out(const int* __restrict__ src,
                           const int* __restrict__ dst,
                           float* __restrict__ out, int E, int half) {
    int t = blockIdx.x * blockDim.x + threadIdx.x;   // over half * 4
    if (t >= half * 4) return;
    int e = t >> 2;
    int q = t & 3;
    int e2 = e + half;

#pragma unroll
    for (int rep = 0; rep < 2; rep++) {
        int ee = rep ? e2 : e;
        if (rep && e2 >= E) break;
        int ns = src[ee];
        int nd = dst[ee];
        uint4 ra = *(const uint4*)&g_gh[ns * D + q * 8];
        uint4 rc = *(const uint4*)&g_gh[nd * D + q * 8];
        float2 a0 = __half22float2(*(__half2*)&ra.x);
        float2 a1 = __half22float2(*(__half2*)&ra.y);
        float2 a2 = __half22float2(*(__half2*)&ra.z);
        float2 a3 = __half22float2(*(__half2*)&ra.w);
        float2 c0 = __half22float2(*(__half2*)&rc.x);
        float2 c1 = __half22float2(*(__half2*)&rc.y);
        float2 c2 = __half22float2(*(__half2*)&rc.z);
        float2 c3 = __half22float2(*(__half2*)&rc.w);
        float4 o0 = make_float4(a0.x + c0.x, a0.y + c0.y, a1.x + c1.x, a1.y + c1.y);
        float4 o1 = make_float4(a2.x + c2.x, a2.y + c2.y, a3.x + c3.x, a3.y + c3.y);
        st_cs_v4((float4*)&out[ee * D + q * 8], o0);
        st_cs_v4((float4*)&out[ee * D + q * 8 + 4], o1);
    }
}

// ---------------------------------------------------------------------------
// Launch
// ---------------------------------------------------------------------------
extern "C" void kernel_launch(void* const* d_in, const int* in_sizes, int n_in,
                              void* d_out, int out_size) {
    const float* edge_feats = (const float*)d_in[0];
    const int*   src        = (const int*)d_in[1];
    const int*   dst        = (const int*)d_in[2];
    const float* W          = (const float*)d_in[3];
    const float* b          = (const float*)d_in[4];

    const int E    = in_sizes[1];
    const int half = (E + 1) / 2;
    const int TPB  = 256;

    const int node_v4      = N_NODES * D4;           // 400K
    const int node_threads = N_NODES * 32;           // warp per node
    const int half_v4      = half * D4;              // K2 domain
    const int half_q       = half * 4;               // K4/K5 domain
    const int cvt_threads  = N_NODES * D / 8;        // 200K

    k_zero<<<(node_v4 + TPB - 1) / TPB, TPB>>>();
    k_scatter_feats<<<(half_v4 + TPB - 1) / TPB, TPB>>>(
        (const float4*)edge_feats, dst, E, half);
    k_norm_gemm<<<(node_threads + TPB - 1) / TPB, TPB>>>(W, b);
    k_gather_scatter<<<(half_q + TPB - 1) / TPB, TPB>>>(src, dst, E, half);
    k_cvt<<<(cvt_threads + TPB - 1) / TPB, TPB>>>();
    k_edge_out<<<(half_q + TPB - 1) / TPB, TPB>>>(src, dst, (float*)d_out, E, half);
}

// round 7
// speedup vs baseline: 1.1917x; 1.1917x over previous
#include <cuda_runtime.h>
#include <cuda_fp16.h>

#define N_NODES 50000
#define D 32
#define D4 8

// Scratch (device globals — no allocation allowed).
__device__ float  g_seg[N_NODES * D];   // step1 fp32 accumulator
__device__ float  g_deg[N_NODES];       // in-degree
__device__ float  g_g[N_NODES * D];     // fp32 accumulator: b/2 + sum 0.5*(mW)[src]
__device__ __half g_sh[N_NODES * D];    // fp16 table: 0.5*(m W^T)   (K4 gathers)
__device__ __half g_gh[N_NODES * D];    // fp16 table: copy of g_g   (K5 gathers)

__device__ __forceinline__ void red_add_v4(float* ptr, float4 v) {
    asm volatile("red.global.add.v4.f32 [%0], {%1, %2, %3, %4};"
                 :: "l"(ptr), "f"(v.x), "f"(v.y), "f"(v.z), "f"(v.w)
                 : "memory");
}

__device__ __forceinline__ float4 ld_cs_v4(const float4* ptr) {
    float4 v;
    asm volatile("ld.global.cs.v4.f32 {%0, %1, %2, %3}, [%4];"
                 : "=f"(v.x), "=f"(v.y), "=f"(v.z), "=f"(v.w) : "l"(ptr));
    return v;
}

__device__ __forceinline__ void st_cs_v4(float4* ptr, float4 v) {
    asm volatile("st.global.cs.v4.f32 [%0], {%1, %2, %3, %4};"
                 :: "l"(ptr), "f"(v.x), "f"(v.y), "f"(v.z), "f"(v.w)
                 : "memory");
}

// 8B fp16 quarter-row load -> float4
__device__ __forceinline__ float4 ld_h4(const __half* p) {
    uint2 raw = *(const uint2*)p;
    float2 f0 = __half22float2(*(__half2*)&raw.x);
    float2 f1 = __half22float2(*(__half2*)&raw.y);
    return make_float4(f0.x, f0.y, f1.x, f1.y);
}

// ---------------------------------------------------------------------------
// K1: g_seg = 0, deg = 0
// ---------------------------------------------------------------------------
__global__ void k_zero() {
    int i = blockIdx.x * blockDim.x + threadIdx.x;   // over N_NODES * D4
    if (i < N_NODES * D4)
        ((float4*)g_seg)[i] = make_float4(0.f, 0.f, 0.f, 0.f);
    if (i < N_NODES) g_deg[i] = 0.0f;
}

// ---------------------------------------------------------------------------
// K2: seg[dst] += ef[e]; deg[dst] += 1.  8 threads/edge (float4), ILP=2.
// (unchanged from round-5: fp32, measured fast)
// ---------------------------------------------------------------------------
__global__ void k_scatter_feats(const float4* __restrict__ ef,
                                const int* __restrict__ dst, int E, int half) {
    int t = blockIdx.x * blockDim.x + threadIdx.x;   // over half * D4
    if (t >= half * D4) return;
    int e  = t >> 3;
    int d4 = t & 7;
    int e2 = e + half;

    float4 v0 = ld_cs_v4(&ef[e * D4 + d4]);
    int n0 = dst[e];
    if (e2 < E) {
        float4 v1 = ld_cs_v4(&ef[e2 * D4 + d4]);
        int n1 = dst[e2];
        red_add_v4(&g_seg[n0 * D + d4 * 4], v0);
        red_add_v4(&g_seg[n1 * D + d4 * 4], v1);
        if (d4 == 0) {
            atomicAdd(&g_deg[n0], 1.0f);
            atomicAdd(&g_deg[n1], 1.0f);
        }
    } else {
        red_add_v4(&g_seg[n0 * D + d4 * 4], v0);
        if (d4 == 0) atomicAdd(&g_deg[n0], 1.0f);
    }
}

// ---------------------------------------------------------------------------
// K3: m = seg/max(deg,1); g_sh row <- fp16(0.5 * m @ W^T); g_g row <- b/2.
// ---------------------------------------------------------------------------
__global__ void k_norm_gemm(const float* __restrict__ W,
                            const float* __restrict__ b) {
    __shared__ float Ws[D * (D + 1)];
    __shared__ float ms[8][D];
    for (int i = threadIdx.x; i < D * D; i += blockDim.x)
        Ws[(i / D) * (D + 1) + (i % D)] = W[i];
    __syncthreads();

    int w = (blockIdx.x * blockDim.x + threadIdx.x) >> 5;
    if (w >= N_NODES) return;
    int lane = threadIdx.x & 31;
    int wib  = (threadIdx.x >> 5) & 7;

    float inv = 1.0f / fmaxf(g_deg[w], 1.0f);
    ms[wib][lane] = g_seg[w * D + lane] * inv;
    __syncwarp();
    float acc = 0.0f;
#pragma unroll
    for (int k = 0; k < D; k++)
        acc = fmaf(ms[wib][k], Ws[lane * (D + 1) + k], acc);
    g_sh[w * D + lane] = __float2half(0.5f * acc);
    g_g[w * D + lane]  = 0.5f * b[lane];
}

// ---------------------------------------------------------------------------
// K4: g_g[dst] += s[src]. Round-5 shape (8 threads/edge, ILP=2), but the
// gather is now an 8B fp16 load. Atomics stay fp32 v4.
// ---------------------------------------------------------------------------
__global__ void k_gather_scatter(const int* __restrict__ src,
                                 const int* __restrict__ dst, int E, int half) {
    int t = blockIdx.x * blockDim.x + threadIdx.x;   // over half * D4
    if (t >= half * D4) return;
    int e  = t >> 3;
    int d4 = t & 7;
    int e2 = e + half;

    int ns0 = src[e];
    int nd0 = dst[e];
    float4 v0 = ld_h4(&g_sh[ns0 * D + d4 * 4]);
    if (e2 < E) {
        int ns1 = src[e2];
        int nd1 = dst[e2];
        float4 v1 = ld_h4(&g_sh[ns1 * D + d4 * 4]);
        red_add_v4(&g_g[nd0 * D + d4 * 4], v0);
        red_add_v4(&g_g[nd1 * D + d4 * 4], v1);
    } else {
        red_add_v4(&g_g[nd0 * D + d4 * 4], v0);
    }
}

// ---------------------------------------------------------------------------
// K4b: convert g_g -> fp16 copy for the K5 gathers
// ---------------------------------------------------------------------------
__global__ void k_cvt() {
    int i = blockIdx.x * blockDim.x + threadIdx.x;   // over N_NODES * D / 8
    if (i >= N_NODES * D / 8) return;
    float4 a = ((const float4*)g_g)[2 * i];
    float4 c = ((const float4*)g_g)[2 * i + 1];
    uint4 o;
    *(__half2*)&o.x = __floats2half2_rn(a.x, a.y);
    *(__half2*)&o.y = __floats2half2_rn(a.z, a.w);
    *(__half2*)&o.z = __floats2half2_rn(c.x, c.y);
    *(__half2*)&o.w = __floats2half2_rn(c.z, c.w);
    ((uint4*)g_gh)[i] = o;
}

// ---------------------------------------------------------------------------
// K5: out[e] = g[src[e]] + g[dst[e]].  Round-5 shape (8 threads/edge, ILP=2);
// gathers are 8B fp16, add fp32, 16B streaming store.
// ---------------------------------------------------------------------------
__global__ void k_edge_out(const int* __restrict__ src,
                           const int* __restrict__ dst,
                           float* __restrict__ out, int E, int half) {
    int t = blockIdx.x * blockDim.x + threadIdx.x;   // over half * D4
    if (t >= half * D4) return;
    int e  = t >> 3;
    int d4 = t & 7;
    int e2 = e + half;

    int ns0 = src[e];
    int nd0 = dst[e];
    float4 a0 = ld_h4(&g_gh[ns0 * D + d4 * 4]);
    float4 c0 = ld_h4(&g_gh[nd0 * D + d4 * 4]);
    float4 o0 = make_float4(a0.x + c0.x, a0.y + c0.y, a0.z + c0.z, a0.w + c0.w);

    if (e2 < E) {
        int ns1 = src[e2];
        int nd1 = dst[e2];
        float4 a1 = ld_h4(&g_gh[ns1 * D + d4 * 4]);
        float4 c1 = ld_h4(&g_gh[nd1 * D + d4 * 4]);
        float4 o1 = make_float4(a1.x + c1.x, a1.y + c1.y, a1.z + c1.z, a1.w + c1.w);
        st_cs_v4((float4*)&out[e * D + d4 * 4], o0);
        st_cs_v4((float4*)&out[e2 * D + d4 * 4], o1);
    } else {
        st_cs_v4((float4*)&out[e * D + d4 * 4], o0);
    }
}

// ---------------------------------------------------------------------------
// Launch
// ---------------------------------------------------------------------------
extern "C" void kernel_launch(void* const* d_in, const int* in_sizes, int n_in,
                              void* d_out, int out_size) {
    const float* edge_feats = (const float*)d_in[0];
    const int*   src        = (const int*)d_in[1];
    const int*   dst        = (const int*)d_in[2];
    const float* W          = (const float*)d_in[3];
    const float* b          = (const float*)d_in[4];

    const int E    = in_sizes[1];
    const int half = (E + 1) / 2;
    const int TPB  = 256;

    const int node_v4      = N_NODES * D4;           // 400K
    const int node_threads = N_NODES * 32;           // warp per node
    const int half_v4      = half * D4;              // edge-kernel domain
    const int cvt_threads  = N_NODES * D / 8;        // 200K

    k_zero<<<(node_v4 + TPB - 1) / TPB, TPB>>>();
    k_scatter_feats<<<(half_v4 + TPB - 1) / TPB, TPB>>>(
        (const float4*)edge_feats, dst, E, half);
    k_norm_gemm<<<(node_threads + TPB - 1) / TPB, TPB>>>(W, b);
    k_gather_scatter<<<(half_v4 + TPB - 1) / TPB, TPB>>>(src, dst, E, half);
    k_cvt<<<(cvt_threads + TPB - 1) / TPB, TPB>>>();
    k_edge_out<<<(half_v4 + TPB - 1) / TPB, TPB>>>(src, dst, (float*)d_out, E, half);
}

// round 8
// speedup vs baseline: 1.2580x; 1.0557x over previous
#include <cuda_runtime.h>
#include <cuda_bf16.h>

#define N_NODES 50000
#define D 32
#define D4 8

// Scratch (device globals — no allocation allowed).
__device__ float g_seg[N_NODES * D];   // step1 accumulator -> 0.5*(m W^T) (in place)
__device__ float g_deg[N_NODES];       // in-degree
__device__ float g_g[N_NODES * D];     // init b/2, += 0.5*(m W^T)[src]

__device__ __forceinline__ void red_add_v4(float* ptr, float4 v) {
    asm volatile("red.global.add.v4.f32 [%0], {%1, %2, %3, %4};"
                 :: "l"(ptr), "f"(v.x), "f"(v.y), "f"(v.z), "f"(v.w)
                 : "memory");
}

__device__ __forceinline__ float4 ld_cs_v4(const float4* ptr) {
    float4 v;
    asm volatile("ld.global.cs.v4.f32 {%0, %1, %2, %3}, [%4];"
                 : "=f"(v.x), "=f"(v.y), "=f"(v.z), "=f"(v.w) : "l"(ptr));
    return v;
}

__device__ __forceinline__ void st_cs_v4(float4* ptr, float4 v) {
    asm volatile("st.global.cs.v4.f32 [%0], {%1, %2, %3, %4};"
                 :: "l"(ptr), "f"(v.x), "f"(v.y), "f"(v.z), "f"(v.w)
                 : "memory");
}

// ---------------------------------------------------------------------------
// K1: g_seg = 0, deg = 0, g_g rows = b/2 (bias+0.5 folded into init)
// ---------------------------------------------------------------------------
__global__ void k_zero(const float* __restrict__ b) {
    int i = blockIdx.x * blockDim.x + threadIdx.x;   // over N_NODES * D4
    if (i < N_NODES * D4) {
        ((float4*)g_seg)[i] = make_float4(0.f, 0.f, 0.f, 0.f);
        float4 bb = *(const float4*)&b[(i & 7) * 4];
        bb.x *= 0.5f; bb.y *= 0.5f; bb.z *= 0.5f; bb.w *= 0.5f;
        ((float4*)g_g)[i] = bb;
    }
    if (i < N_NODES) g_deg[i] = 0.0f;
}

// ---------------------------------------------------------------------------
// K2: seg[dst] += ef[e]; deg[dst] += 1.  8 threads/edge, ILP=4.
// All 4 loads + 4 index loads issued before any REDG (front-batched MLP).
// ---------------------------------------------------------------------------
__global__ void k_scatter_feats(const float4* __restrict__ ef,
                                const int* __restrict__ dst, int E, int q) {
    int t = blockIdx.x * blockDim.x + threadIdx.x;   // over q * D4
    if (t >= q * D4) return;
    int e0 = t >> 3;
    int d4 = t & 7;
    int e1 = e0 + q, e2 = e0 + 2 * q, e3 = e0 + 3 * q;

    // front-batch loads (independent)
    float4 v0 = ld_cs_v4(&ef[e0 * D4 + d4]);
    int n0 = dst[e0];
    float4 v1, v2, v3;
    int n1 = 0, n2 = 0, n3 = 0;
    bool p1 = e1 < E, p2 = e2 < E, p3 = e3 < E;
    if (p1) { v1 = ld_cs_v4(&ef[e1 * D4 + d4]); n1 = dst[e1]; }
    if (p2) { v2 = ld_cs_v4(&ef[e2 * D4 + d4]); n2 = dst[e2]; }
    if (p3) { v3 = ld_cs_v4(&ef[e3 * D4 + d4]); n3 = dst[e3]; }

    red_add_v4(&g_seg[n0 * D + d4 * 4], v0);
    if (p1) red_add_v4(&g_seg[n1 * D + d4 * 4], v1);
    if (p2) red_add_v4(&g_seg[n2 * D + d4 * 4], v2);
    if (p3) red_add_v4(&g_seg[n3 * D + d4 * 4], v3);
    if (d4 == 0) {
        atomicAdd(&g_deg[n0], 1.0f);
        if (p1) atomicAdd(&g_deg[n1], 1.0f);
        if (p2) atomicAdd(&g_deg[n2], 1.0f);
        if (p3) atomicAdd(&g_deg[n3], 1.0f);
    }
}

// ---------------------------------------------------------------------------
// K3: m = seg/max(deg,1); g_seg row <- 0.5 * (m @ W^T)  (warp per node)
// ---------------------------------------------------------------------------
__global__ void k_norm_gemm(const float* __restrict__ W) {
    __shared__ float Ws[D * (D + 1)];
    __shared__ float ms[8][D];
    for (int i = threadIdx.x; i < D * D; i += blockDim.x)
        Ws[(i / D) * (D + 1) + (i % D)] = W[i];
    __syncthreads();

    int w = (blockIdx.x * blockDim.x + threadIdx.x) >> 5;
    if (w >= N_NODES) return;
    int lane = threadIdx.x & 31;
    int wib  = (threadIdx.x >> 5) & 7;

    float inv = 1.0f / fmaxf(g_deg[w], 1.0f);
    ms[wib][lane] = g_seg[w * D + lane] * inv;
    __syncwarp();
    float acc = 0.0f;
#pragma unroll
    for (int k = 0; k < D; k++)
        acc = fmaf(ms[wib][k], Ws[lane * (D + 1) + k], acc);
    g_seg[w * D + lane] = 0.5f * acc;
}

// ---------------------------------------------------------------------------
// K4: g_g[dst] += g_seg[src].  8 threads/edge, ILP=4, front-batched gathers.
// ---------------------------------------------------------------------------
__global__ void k_gather_scatter(const int* __restrict__ src,
                                 const int* __restrict__ dst, int E, int q) {
    int t = blockIdx.x * blockDim.x + threadIdx.x;   // over q * D4
    if (t >= q * D4) return;
    int e0 = t >> 3;
    int d4 = t & 7;
    int e1 = e0 + q, e2 = e0 + 2 * q, e3 = e0 + 3 * q;
    bool p1 = e1 < E, p2 = e2 < E, p3 = e3 < E;

    int ns0 = src[e0], nd0 = dst[e0];
    int ns1 = 0, nd1 = 0, ns2 = 0, nd2 = 0, ns3 = 0, nd3 = 0;
    if (p1) { ns1 = src[e1]; nd1 = dst[e1]; }
    if (p2) { ns2 = src[e2]; nd2 = dst[e2]; }
    if (p3) { ns3 = src[e3]; nd3 = dst[e3]; }

    float4 v0 = *(const float4*)&g_seg[ns0 * D + d4 * 4];
    float4 v1, v2, v3;
    if (p1) v1 = *(const float4*)&g_seg[ns1 * D + d4 * 4];
    if (p2) v2 = *(const float4*)&g_seg[ns2 * D + d4 * 4];
    if (p3) v3 = *(const float4*)&g_seg[ns3 * D + d4 * 4];

    red_add_v4(&g_g[nd0 * D + d4 * 4], v0);
    if (p1) red_add_v4(&g_g[nd1 * D + d4 * 4], v1);
    if (p2) red_add_v4(&g_g[nd2 * D + d4 * 4], v2);
    if (p3) red_add_v4(&g_g[nd3 * D + d4 * 4], v3);
}

// ---------------------------------------------------------------------------
// K5: out[e] = g_g[src[e]] + g_g[dst[e]].  8 threads/edge, ILP=4.
// 8 independent gathers in flight, then 4 streaming stores.
// ---------------------------------------------------------------------------
__global__ void k_edge_out(const int* __restrict__ src,
                           const int* __restrict__ dst,
                           float4* __restrict__ out, int E, int q) {
    int t = blockIdx.x * blockDim.x + threadIdx.x;   // over q * D4
    if (t >= q * D4) return;
    int e0 = t >> 3;
    int d4 = t & 7;
    int e1 = e0 + q, e2 = e0 + 2 * q, e3 = e0 + 3 * q;
    bool p1 = e1 < E, p2 = e2 < E, p3 = e3 < E;

    int ns0 = src[e0], nd0 = dst[e0];
    int ns1 = 0, nd1 = 0, ns2 = 0, nd2 = 0, ns3 = 0, nd3 = 0;
    if (p1) { ns1 = src[e1]; nd1 = dst[e1]; }
    if (p2) { ns2 = src[e2]; nd2 = dst[e2]; }
    if (p3) { ns3 = src[e3]; nd3 = dst[e3]; }

    float4 a0 = *(const float4*)&g_g[ns0 * D + d4 * 4];
    float4 c0 = *(const float4*)&g_g[nd0 * D + d4 * 4];
    float4 a1, c1, a2, c2, a3, c3;
    if (p1) { a1 = *(const float4*)&g_g[ns1 * D + d4 * 4];
              c1 = *(const float4*)&g_g[nd1 * D + d4 * 4]; }
    if (p2) { a2 = *(const float4*)&g_g[ns2 * D + d4 * 4];
              c2 = *(const float4*)&g_g[nd2 * D + d4 * 4]; }
    if (p3) { a3 = *(const float4*)&g_g[ns3 * D + d4 * 4];
              c3 = *(const float4*)&g_g[nd3 * D + d4 * 4]; }

    float4 o0 = make_float4(a0.x + c0.x, a0.y + c0.y, a0.z + c0.z, a0.w + c0.w);
    st_cs_v4(&out[e0 * D4 + d4], o0);
    if (p1) {
        float4 o1 = make_float4(a1.x + c1.x, a1.y + c1.y, a1.z + c1.z, a1.w + c1.w);
        st_cs_v4(&out[e1 * D4 + d4], o1);
    }
    if (p2) {
        float4 o2 = make_float4(a2.x + c2.x, a2.y + c2.y, a2.z + c2.z, a2.w + c2.w);
        st_cs_v4(&out[e2 * D4 + d4], o2);
    }
    if (p3) {
        float4 o3 = make_float4(a3.x + c3.x, a3.y + c3.y, a3.z + c3.z, a3.w + c3.w);
        st_cs_v4(&out[e3 * D4 + d4], o3);
    }
}

// ---------------------------------------------------------------------------
// Launch
// ---------------------------------------------------------------------------
extern "C" void kernel_launch(void* const* d_in, const int* in_sizes, int n_in,
                              void* d_out, int out_size) {
    const float* edge_feats = (const float*)d_in[0];
    const int*   src        = (const int*)d_in[1];
    const int*   dst        = (const int*)d_in[2];
    const float* W          = (const float*)d_in[3];
    const float* b          = (const float*)d_in[4];

    const int E   = in_sizes[1];
    const int q   = (E + 3) / 4;
    const int TPB = 256;

    const int node_v4      = N_NODES * D4;
    const int node_threads = N_NODES * 32;
    const int q_v4         = q * D4;

    k_zero<<<(node_v4 + TPB - 1) / TPB, TPB>>>(b);
    k_scatter_feats<<<(q_v4 + TPB - 1) / TPB, TPB>>>(
        (const float4*)edge_feats, dst, E, q);
    k_norm_gemm<<<(node_threads + TPB - 1) / TPB, TPB>>>(W);
    k_gather_scatter<<<(q_v4 + TPB - 1) / TPB, TPB>>>(src, dst, E, q);
    k_edge_out<<<(q_v4 + TPB - 1) / TPB, TPB>>>(src, dst, (float4*)d_out, E, q);
}